// round 4
// baseline (speedup 1.0000x reference)
#include <cuda_runtime.h>

// GRU, T=365 steps, 65536 independent cells, HID=64.
// One persistent kernel; thread = one cell. Hidden state lives BOTH in
// registers (packed f32x2, fixed-index use in the unrolled k-loop only) and
// in a ping-pong shared-memory copy (for the dynamically-indexed h_old[j]
// read and the hnew staging). The j-loop is rolled to keep register
// pressure under the launch-bounds cap (R2 spilled 44KB/thread with it
// fully unrolled).

#define NC (256 * 256)
#define TT 365

__device__ __forceinline__ void ffma2(unsigned long long& d,
                                      unsigned long long a,
                                      unsigned long long b) {
    asm("fma.rn.f32x2 %0, %1, %2, %0;" : "+l"(d) : "l"(a), "l"(b));
}

__device__ __forceinline__ unsigned long long addf2(unsigned long long a,
                                                    unsigned long long b) {
    unsigned long long r;
    asm("add.rn.f32x2 %0, %1, %2;" : "=l"(r) : "l"(a), "l"(b));
    return r;
}

__device__ __forceinline__ unsigned long long pack2(float lo, float hi) {
    unsigned long long r;
    asm("mov.b64 %0, {%1, %2};" : "=l"(r) : "f"(lo), "f"(hi));
    return r;
}

__device__ __forceinline__ float2 unpack2(unsigned long long v) {
    float2 r;
    asm("mov.b64 {%0, %1}, %2;" : "=f"(r.x), "=f"(r.y) : "l"(v));
    return r;
}

// Pre-activations bounded (weights ~U(+-0.125), h in (-1,1), x in ~(-4,4)),
// so fast-math exp/div never hit edge cases at our 1e-3 tolerance.
__device__ __forceinline__ float sigf(float x) {
    return __fdividef(1.0f, 1.0f + __expf(-x));
}

__device__ __forceinline__ float tanh_acc(float x) {
    float a = fabsf(x);
    float e = __expf(-2.0f * a);
    float t = __fdividef(1.0f - e, 1.0f + e);
    return copysignf(t, x);
}

__global__ void __launch_bounds__(64, 5)
gru_persist(const float* __restrict__ precip,
            const float* __restrict__ temp,
            const float* __restrict__ wih,     // (192, 2)
            const float* __restrict__ whh,     // (192, 64)
            const float* __restrict__ bias,    // (192,)
            const float* __restrict__ bias_n,  // (64,)
            const float* __restrict__ out_w,   // (1, 64)
            const float* __restrict__ out_b,   // (1,)
            const float* __restrict__ init_h,  // (64,)
            float* __restrict__ out)           // smb (365*65536) ++ final_h (65536*64)
{
    __shared__ float s_wih[384];
    __shared__ float s_bias[192];
    __shared__ float s_bn[64];
    __shared__ float s_ow[64];
    // Ping-pong hidden-state staging: column `tid` is thread-private.
    // Addr pattern j*64+tid -> lanes consecutive -> conflict-free.
    __shared__ float s_h[2][64 * 64];

    const int tid = threadIdx.x;
    const int c = blockIdx.x * 64 + tid;

    for (int i = tid; i < 384; i += 64) s_wih[i] = wih[i];
    for (int i = tid; i < 192; i += 64) s_bias[i] = bias[i];
    s_bn[tid] = bias_n[tid];
    s_ow[tid] = out_w[tid];
    __syncthreads();

    const float ob = out_b[0];

    // Register copy of h (used ONLY at fixed indices in the k-loop).
    unsigned long long h[32];
#pragma unroll
    for (int i = 0; i < 32; i++) {
        float a = init_h[2 * i];
        float b = init_h[2 * i + 1];
        h[i] = pack2(a, b);
        s_h[0][(2 * i) * 64 + tid] = a;
        s_h[0][(2 * i + 1) * 64 + tid] = b;
    }

    int tp = 0;
    for (int t = 0; t < TT; t++) {
        const float xp = precip[t * NC + c];
        const float xt = temp[t * NC + c];
        float y = ob;

        const float* hold_col = &s_h[tp][tid];
        float* hnew_col = &s_h[tp ^ 1][tid];

#pragma unroll 1
        for (int j = 0; j < 64; j++) {
            // Three gate rows (r, z, n) of W_hh; broadcast LDG.128 (same
            // address across the warp), L1-resident (W_hh = 48 KB).
            const ulonglong2* wr = (const ulonglong2*)(whh + j * 64);
            const ulonglong2* wz = (const ulonglong2*)(whh + (j + 64) * 64);
            const ulonglong2* wn = (const ulonglong2*)(whh + (j + 128) * 64);
            unsigned long long ar0 = 0, ar1 = 0;
            unsigned long long az0 = 0, az1 = 0;
            unsigned long long an0 = 0, an1 = 0;
#pragma unroll
            for (int k = 0; k < 16; k++) {
                const ulonglong2 a = wr[k];
                const ulonglong2 b = wz[k];
                const ulonglong2 d = wn[k];
                ffma2(ar0, h[2 * k],     a.x);
                ffma2(ar1, h[2 * k + 1], a.y);
                ffma2(az0, h[2 * k],     b.x);
                ffma2(az1, h[2 * k + 1], b.y);
                ffma2(an0, h[2 * k],     d.x);
                ffma2(an1, h[2 * k + 1], d.y);
            }
            const float2 pr = unpack2(addf2(ar0, ar1));
            const float2 pz = unpack2(addf2(az0, az1));
            const float2 pn = unpack2(addf2(an0, an1));
            const float hr  = pr.x + pr.y;
            const float hz  = pz.x + pz.y;
            const float hnv = pn.x + pn.y;

            // igates: x @ W_ih^T + bias  (W_ih is (192,2) row-major)
            const float igr = fmaf(xp, s_wih[2 * j],
                              fmaf(xt, s_wih[2 * j + 1], s_bias[j]));
            const float igz = fmaf(xp, s_wih[2 * j + 128],
                              fmaf(xt, s_wih[2 * j + 129], s_bias[j + 64]));
            const float ign = fmaf(xp, s_wih[2 * j + 256],
                              fmaf(xt, s_wih[2 * j + 257], s_bias[j + 128]));

            const float r = sigf(igr + hr);
            const float z = sigf(igz + hz);
            const float n = tanh_acc(fmaf(r, hnv + s_bn[j], ign));
            const float hold = hold_col[j * 64];           // LDS, conflict-free
            // equinox convention: h_next = n + z * (h - n)
            const float hx = fmaf(z, hold - n, n);
            hnew_col[j * 64] = hx;                          // STS, conflict-free
            y = fmaf(hx, s_ow[j], y);
        }

        tp ^= 1;
        // Repack register copy of h from the new smem state (fixed indices).
        const float* nc_ = &s_h[tp][tid];
#pragma unroll
        for (int i = 0; i < 32; i++)
            h[i] = pack2(nc_[(2 * i) * 64], nc_[(2 * i + 1) * 64]);

        out[t * NC + c] = y;  // smb, coalesced
    }

    // final_h: (H, W, 64) contiguous per cell, after the smb block.
    unsigned long long* fh =
        (unsigned long long*)(out + (size_t)TT * NC + (size_t)c * 64);
#pragma unroll
    for (int i = 0; i < 32; i++) fh[i] = h[i];
}

extern "C" void kernel_launch(void* const* d_in, const int* in_sizes, int n_in,
                              void* d_out, int out_size) {
    gru_persist<<<NC / 64, 64>>>(
        (const float*)d_in[0],   // precipitation
        (const float*)d_in[1],   // temperature
        (const float*)d_in[2],   // weight_ih
        (const float*)d_in[3],   // weight_hh
        (const float*)d_in[4],   // bias
        (const float*)d_in[5],   // bias_n
        (const float*)d_in[6],   // out_w
        (const float*)d_in[7],   // out_b
        (const float*)d_in[8],   // init_h
        (float*)d_out);
}

// round 5
// speedup vs baseline: 2.9554x; 2.9554x over previous
#include <cuda_runtime.h>

// GRU, T=365, 65536 independent cells, HID=64. Thread = one cell.
// R4 lesson: broadcast LDG.128 of W_hh was the wall (L1 52%, fma 14.5%).
// This round: W_hh lives in shared memory (broadcast LDS.128), the
// dynamically-indexed h staging moves to a 256B/thread local array, and
// activations use MUFU tanh.approx. 128-thr blocks, 3 blocks/SM.

#define NC (256 * 256)
#define TT 365

__device__ __forceinline__ void ffma2(unsigned long long& d,
                                      unsigned long long a,
                                      unsigned long long b) {
    asm("fma.rn.f32x2 %0, %1, %2, %0;" : "+l"(d) : "l"(a), "l"(b));
}

__device__ __forceinline__ unsigned long long addf2(unsigned long long a,
                                                    unsigned long long b) {
    unsigned long long r;
    asm("add.rn.f32x2 %0, %1, %2;" : "=l"(r) : "l"(a), "l"(b));
    return r;
}

__device__ __forceinline__ unsigned long long pack2(float lo, float hi) {
    unsigned long long r;
    asm("mov.b64 %0, {%1, %2};" : "=l"(r) : "f"(lo), "f"(hi));
    return r;
}

__device__ __forceinline__ float2 unpack2(unsigned long long v) {
    float2 r;
    asm("mov.b64 {%0, %1}, %2;" : "=f"(r.x), "=f"(r.y) : "l"(v));
    return r;
}

// MUFU.TANH (sm_75+): ~1e-5 accuracy, 1 MUFU op. Tolerance is 1e-3 and the
// fp32 version measured 3.6e-7, so there is ample headroom.
__device__ __forceinline__ float tanh_fast(float x) {
    float r;
    asm("tanh.approx.f32 %0, %1;" : "=f"(r) : "f"(x));
    return r;
}

__device__ __forceinline__ float sig_fast(float x) {
    return fmaf(0.5f, tanh_fast(0.5f * x), 0.5f);
}

__global__ void __launch_bounds__(128, 3)
gru_persist(const float* __restrict__ precip,
            const float* __restrict__ temp,
            const float* __restrict__ wih,     // (192, 2)
            const float* __restrict__ whh,     // (192, 64)
            const float* __restrict__ bias,    // (192,)
            const float* __restrict__ bias_n,  // (64,)
            const float* __restrict__ out_w,   // (1, 64)
            const float* __restrict__ out_b,   // (1,)
            const float* __restrict__ init_h,  // (64,)
            float* __restrict__ out)           // smb (365*65536) ++ final_h (65536*64)
{
    __shared__ float s_w[192 * 64];   // W_hh, 48 KB
    __shared__ float s_wih[384];
    __shared__ float s_bias[192];
    __shared__ float s_bn[64];
    __shared__ float s_ow[64];

    const int tid = threadIdx.x;
    const int c = blockIdx.x * 128 + tid;

    for (int i = tid; i < 192 * 64; i += 128) s_w[i] = whh[i];
    for (int i = tid; i < 384; i += 128) s_wih[i] = wih[i];
    for (int i = tid; i < 192; i += 128) s_bias[i] = bias[i];
    if (tid < 64) {
        s_bn[tid] = bias_n[tid];
        s_ow[tid] = out_w[tid];
    }
    __syncthreads();

    const float ob = out_b[0];

    // Register copy of h: used ONLY at fixed indices inside the k-loop.
    unsigned long long h[32];
    // Local (per-thread stack, 256B) copy: serves the dynamically-indexed
    // h_old[j] read and the hnew[j] staging write. In-place RMW is safe:
    // iteration j overwrites slot j, later iterations only read j' > j, and
    // the k-loop reads the register copy.
    float l_h[64];
#pragma unroll
    for (int i = 0; i < 32; i++) {
        float a = init_h[2 * i];
        float b = init_h[2 * i + 1];
        h[i] = pack2(a, b);
        l_h[2 * i] = a;
        l_h[2 * i + 1] = b;
    }

    for (int t = 0; t < TT; t++) {
        const float xp = precip[t * NC + c];
        const float xt = temp[t * NC + c];
        float y = ob;

#pragma unroll 1
        for (int j = 0; j < 64; j++) {
            // Three gate rows (r, z, n) of W_hh from smem; broadcast
            // LDS.128 (all lanes same address -> N=1, no conflicts).
            const ulonglong2* wr = (const ulonglong2*)(s_w + j * 64);
            const ulonglong2* wz = (const ulonglong2*)(s_w + (j + 64) * 64);
            const ulonglong2* wn = (const ulonglong2*)(s_w + (j + 128) * 64);
            unsigned long long ar0 = 0, ar1 = 0;
            unsigned long long az0 = 0, az1 = 0;
            unsigned long long an0 = 0, an1 = 0;
#pragma unroll
            for (int k = 0; k < 16; k++) {
                const ulonglong2 a = wr[k];
                const ulonglong2 b = wz[k];
                const ulonglong2 d = wn[k];
                ffma2(ar0, h[2 * k],     a.x);
                ffma2(ar1, h[2 * k + 1], a.y);
                ffma2(az0, h[2 * k],     b.x);
                ffma2(az1, h[2 * k + 1], b.y);
                ffma2(an0, h[2 * k],     d.x);
                ffma2(an1, h[2 * k + 1], d.y);
            }
            const float2 pr = unpack2(addf2(ar0, ar1));
            const float2 pz = unpack2(addf2(az0, az1));
            const float2 pn = unpack2(addf2(an0, an1));
            const float hr  = pr.x + pr.y;
            const float hz  = pz.x + pz.y;
            const float hnv = pn.x + pn.y;

            // igates: x @ W_ih^T + bias  (W_ih is (192,2) row-major)
            const float igr = fmaf(xp, s_wih[2 * j],
                              fmaf(xt, s_wih[2 * j + 1], s_bias[j]));
            const float igz = fmaf(xp, s_wih[2 * j + 128],
                              fmaf(xt, s_wih[2 * j + 129], s_bias[j + 64]));
            const float ign = fmaf(xp, s_wih[2 * j + 256],
                              fmaf(xt, s_wih[2 * j + 257], s_bias[j + 128]));

            const float r = sig_fast(igr + hr);
            const float z = sig_fast(igz + hz);
            const float n = tanh_fast(fmaf(r, hnv + s_bn[j], ign));
            const float hold = l_h[j];                 // LDL
            // equinox convention: h_next = n + z * (h - n)
            const float hx = fmaf(z, hold - n, n);
            l_h[j] = hx;                               // STL
            y = fmaf(hx, s_ow[j], y);
        }

        // Rebuild register copy from the updated local state.
#pragma unroll
        for (int i = 0; i < 32; i++)
            h[i] = pack2(l_h[2 * i], l_h[2 * i + 1]);

        out[t * NC + c] = y;  // smb, coalesced
    }

    // final_h: (H, W, 64) contiguous per cell, after the smb block.
    unsigned long long* fh =
        (unsigned long long*)(out + (size_t)TT * NC + (size_t)c * 64);
#pragma unroll
    for (int i = 0; i < 32; i++) fh[i] = h[i];
}

extern "C" void kernel_launch(void* const* d_in, const int* in_sizes, int n_in,
                              void* d_out, int out_size) {
    gru_persist<<<NC / 128, 128>>>(
        (const float*)d_in[0],   // precipitation
        (const float*)d_in[1],   // temperature
        (const float*)d_in[2],   // weight_ih
        (const float*)d_in[3],   // weight_hh
        (const float*)d_in[4],   // bias
        (const float*)d_in[5],   // bias_n
        (const float*)d_in[6],   // out_w
        (const float*)d_in[7],   // out_b
        (const float*)d_in[8],   // init_h
        (float*)d_out);
}

// round 7
// speedup vs baseline: 3.8664x; 1.3082x over previous
#include <cuda_runtime.h>

// GRU, T=365, 65536 cells, HID=64. One persistent kernel.
// R5 lesson: smem weight reads (48 broadcast LDS.128 per j) were the wall
// (L1=82%, fma=41%). This round each thread owns TWO cells, so every weight
// load feeds 2x the FMAs: LDS-per-FMA halves, fma pipe becomes the binder.

#define NC (256 * 256)
#define TT 365

__device__ __forceinline__ void ffma2(unsigned long long& d,
                                      unsigned long long a,
                                      unsigned long long b) {
    asm("fma.rn.f32x2 %0, %1, %2, %0;" : "+l"(d) : "l"(a), "l"(b));
}

__device__ __forceinline__ unsigned long long addf2(unsigned long long a,
                                                    unsigned long long b) {
    unsigned long long r;
    asm("add.rn.f32x2 %0, %1, %2;" : "=l"(r) : "l"(a), "l"(b));
    return r;
}

__device__ __forceinline__ unsigned long long pack2(float lo, float hi) {
    unsigned long long r;
    asm("mov.b64 %0, {%1, %2};" : "=l"(r) : "f"(lo), "f"(hi));
    return r;
}

__device__ __forceinline__ float2 unpack2(unsigned long long v) {
    float2 r;
    asm("mov.b64 {%0, %1}, %2;" : "=f"(r.x), "=f"(r.y) : "l"(v));
    return r;
}

// MUFU.TANH: ~1e-5 accuracy; tolerance is 1e-3 (R5 measured 3.5e-6).
__device__ __forceinline__ float tanh_fast(float x) {
    float r;
    asm("tanh.approx.f32 %0, %1;" : "=f"(r) : "f"(x));
    return r;
}

__device__ __forceinline__ float sig_fast(float x) {
    return fmaf(0.5f, tanh_fast(0.5f * x), 0.5f);
}

__global__ void __launch_bounds__(128, 2)
gru_persist(const float* __restrict__ precip,
            const float* __restrict__ temp,
            const float* __restrict__ wih,     // (192, 2)
            const float* __restrict__ whh,     // (192, 64)
            const float* __restrict__ bias,    // (192,)
            const float* __restrict__ bias_n,  // (64,)
            const float* __restrict__ out_w,   // (1, 64)
            const float* __restrict__ out_b,   // (1,)
            const float* __restrict__ init_h,  // (64,)
            float* __restrict__ out)           // smb (365*65536) ++ final_h (65536*64)
{
    __shared__ float s_w[192 * 64];   // W_hh, 48 KB
    __shared__ float s_wih[384];
    __shared__ float s_bias[192];
    __shared__ float s_bn[64];
    __shared__ float s_ow[64];

    const int tid = threadIdx.x;
    // Each thread owns two cells: c0 and c0+128 (both coalesced per warp).
    const int c0 = blockIdx.x * 256 + tid;
    const int c1 = c0 + 128;

    for (int i = tid; i < 192 * 64; i += 128) s_w[i] = whh[i];
    for (int i = tid; i < 384; i += 128) s_wih[i] = wih[i];
    for (int i = tid; i < 192; i += 128) s_bias[i] = bias[i];
    if (tid < 64) {
        s_bn[tid] = bias_n[tid];
        s_ow[tid] = out_w[tid];
    }
    __syncthreads();

    const float ob = out_b[0];

    // Register copies of both hidden states: fixed-index use only (k-loop).
    unsigned long long ha[32], hb[32];
    // Local (512B/thread) copies for the dynamically-indexed h_old[j] read
    // and hnew[j] write. In-place RMW safe: slot j written at iter j, later
    // iters read only j' > j; the k-loop reads the register copies.
    float l_ha[64], l_hb[64];
#pragma unroll
    for (int i = 0; i < 32; i++) {
        float a = init_h[2 * i];
        float b = init_h[2 * i + 1];
        ha[i] = pack2(a, b);
        hb[i] = pack2(a, b);
        l_ha[2 * i] = a; l_ha[2 * i + 1] = b;
        l_hb[2 * i] = a; l_hb[2 * i + 1] = b;
    }

    for (int t = 0; t < TT; t++) {
        const float xp0 = precip[t * NC + c0];
        const float xt0 = temp[t * NC + c0];
        const float xp1 = precip[t * NC + c1];
        const float xt1 = temp[t * NC + c1];
        float y0 = ob, y1 = ob;

#pragma unroll 1
        for (int j = 0; j < 64; j++) {
            // Gate rows (r, z, n) of W_hh from smem; broadcast LDS.128.
            const ulonglong2* wr = (const ulonglong2*)(s_w + j * 64);
            const ulonglong2* wz = (const ulonglong2*)(s_w + (j + 64) * 64);
            const ulonglong2* wn = (const ulonglong2*)(s_w + (j + 128) * 64);
            unsigned long long ar0 = 0, ar1 = 0, br0 = 0, br1 = 0;
            unsigned long long az0 = 0, az1 = 0, bz0 = 0, bz1 = 0;
            unsigned long long an0 = 0, an1 = 0, bn0 = 0, bn1 = 0;
#pragma unroll
            for (int k = 0; k < 16; k++) {
                const ulonglong2 a = wr[k];
                const ulonglong2 b = wz[k];
                const ulonglong2 d = wn[k];
                // cell 0
                ffma2(ar0, ha[2 * k],     a.x);
                ffma2(ar1, ha[2 * k + 1], a.y);
                ffma2(az0, ha[2 * k],     b.x);
                ffma2(az1, ha[2 * k + 1], b.y);
                ffma2(an0, ha[2 * k],     d.x);
                ffma2(an1, ha[2 * k + 1], d.y);
                // cell 1 (reuses the same weight registers)
                ffma2(br0, hb[2 * k],     a.x);
                ffma2(br1, hb[2 * k + 1], a.y);
                ffma2(bz0, hb[2 * k],     b.x);
                ffma2(bz1, hb[2 * k + 1], b.y);
                ffma2(bn0, hb[2 * k],     d.x);
                ffma2(bn1, hb[2 * k + 1], d.y);
            }

            // igate scalars (amortized over both cells).
            const float wih_r0 = s_wih[2 * j],       wih_r1 = s_wih[2 * j + 1];
            const float wih_z0 = s_wih[2 * j + 128], wih_z1 = s_wih[2 * j + 129];
            const float wih_n0 = s_wih[2 * j + 256], wih_n1 = s_wih[2 * j + 257];
            const float b_r = s_bias[j], b_z = s_bias[j + 64], b_n = s_bias[j + 128];
            const float bnj = s_bn[j];
            const float owj = s_ow[j];

            // ---- cell 0 ----
            {
                const float2 pr = unpack2(addf2(ar0, ar1));
                const float2 pz = unpack2(addf2(az0, az1));
                const float2 pn = unpack2(addf2(an0, an1));
                const float hr  = pr.x + pr.y;
                const float hz  = pz.x + pz.y;
                const float hnv = pn.x + pn.y;
                const float igr = fmaf(xp0, wih_r0, fmaf(xt0, wih_r1, b_r));
                const float igz = fmaf(xp0, wih_z0, fmaf(xt0, wih_z1, b_z));
                const float ign = fmaf(xp0, wih_n0, fmaf(xt0, wih_n1, b_n));
                const float r = sig_fast(igr + hr);
                const float z = sig_fast(igz + hz);
                const float n = tanh_fast(fmaf(r, hnv + bnj, ign));
                const float hx = fmaf(z, l_ha[j] - n, n);
                l_ha[j] = hx;
                y0 = fmaf(hx, owj, y0);
            }
            // ---- cell 1 ----
            {
                const float2 pr = unpack2(addf2(br0, br1));
                const float2 pz = unpack2(addf2(bz0, bz1));
                const float2 pn = unpack2(addf2(bn0, bn1));
                const float hr  = pr.x + pr.y;
                const float hz  = pz.x + pz.y;
                const float hnv = pn.x + pn.y;
                const float igr = fmaf(xp1, wih_r0, fmaf(xt1, wih_r1, b_r));
                const float igz = fmaf(xp1, wih_z0, fmaf(xt1, wih_z1, b_z));
                const float ign = fmaf(xp1, wih_n0, fmaf(xt1, wih_n1, b_n));
                const float r = sig_fast(igr + hr);
                const float z = sig_fast(igz + hz);
                const float n = tanh_fast(fmaf(r, hnv + bnj, ign));
                const float hx = fmaf(z, l_hb[j] - n, n);
                l_hb[j] = hx;
                y1 = fmaf(hx, owj, y1);
            }
        }

        // Rebuild register copies from updated local state.
#pragma unroll
        for (int i = 0; i < 32; i++) {
            ha[i] = pack2(l_ha[2 * i], l_ha[2 * i + 1]);
            hb[i] = pack2(l_hb[2 * i], l_hb[2 * i + 1]);
        }

        out[t * NC + c0] = y0;  // coalesced
        out[t * NC + c1] = y1;  // coalesced
    }

    // final_h: (H, W, 64) contiguous per cell, after the smb block.
    unsigned long long* f0 =
        (unsigned long long*)(out + (size_t)TT * NC + (size_t)c0 * 64);
    unsigned long long* f1 =
        (unsigned long long*)(out + (size_t)TT * NC + (size_t)c1 * 64);
#pragma unroll
    for (int i = 0; i < 32; i++) {
        f0[i] = ha[i];
        f1[i] = hb[i];
    }
}

extern "C" void kernel_launch(void* const* d_in, const int* in_sizes, int n_in,
                              void* d_out, int out_size) {
    gru_persist<<<NC / 256, 128>>>(
        (const float*)d_in[0],   // precipitation
        (const float*)d_in[1],   // temperature
        (const float*)d_in[2],   // weight_ih
        (const float*)d_in[3],   // weight_hh
        (const float*)d_in[4],   // bias
        (const float*)d_in[5],   // bias_n
        (const float*)d_in[6],   // out_w
        (const float*)d_in[7],   // out_b
        (const float*)d_in[8],   // init_h
        (float*)d_out);
}

// round 13
// speedup vs baseline: 5.7008x; 1.4745x over previous
#include <cuda_runtime.h>
#include <cuda_bf16.h>
#include <cstdint>

// GRU T=365, 65536 cells, HID=64 — legacy tensor core (mma.sync bf16) with a
// fully register-resident recurrence.
//
// Per warp: 16 cells. gates[16,192] = h[16,64] @ Whh^T via m16n8k16 bf16
// mma.sync, 2-term hi/lo split (3 passes, lo*lo dropped) for fp32-class
// precision, fp32 accumulate. The m16n8k16 D fragment (cells x gates) and A
// fragment (cells x hidden) give each thread the SAME (row, col mod 8)
// ownership, and gates r/z/n live at j, j+64, j+128 (same mod 8) — so each
// thread computes h_next for its own positions and repacks next step's A
// fragments entirely in registers. No smem round-trip in the time loop.
//
// R11 root cause: 48KB dynamic + 2.8KB static shared exceeded the 48KB
// default per-block cap -> invalid launch. Fix: ONE dynamic allocation
// (51,968B) + cudaFuncSetAttribute opt-in (immediate host call, not a
// stream op, graph-capture safe, idempotent).

#define NC (256 * 256)
#define TT 365
#define FRAG_BYTES (96 * 32 * 16)  // 96 B-tiles x 32 lanes x uint4 = 49152
#define SMEM_BYTES (FRAG_BYTES + (384 + 192 + 64 + 64) * 4)  // 51968

__device__ __forceinline__ uint32_t pk_bf2(float up, float lo) {
    uint32_t r;
    asm("cvt.rn.bf16x2.f32 %0, %1, %2;" : "=r"(r) : "f"(up), "f"(lo));
    return r;
}
__device__ __forceinline__ float lo16f(uint32_t r) { return __uint_as_float(r << 16); }
__device__ __forceinline__ float hi16f(uint32_t r) { return __uint_as_float(r & 0xffff0000u); }

__device__ __forceinline__ float tanh_fast(float x) {
    float r;
    asm("tanh.approx.f32 %0, %1;" : "=f"(r) : "f"(x));
    return r;
}
__device__ __forceinline__ float sig_fast(float x) {
    return fmaf(0.5f, tanh_fast(0.5f * x), 0.5f);
}

// D += A(bf16) * B(bf16), m16n8k16, fp32 accum.
#define MMA(d, a, b0v, b1v)                                               \
    asm("mma.sync.aligned.m16n8k16.row.col.f32.bf16.bf16.f32 "            \
        "{%0,%1,%2,%3}, {%4,%5,%6,%7}, {%8,%9}, {%0,%1,%2,%3};"           \
        : "+f"((d)[0]), "+f"((d)[1]), "+f"((d)[2]), "+f"((d)[3])          \
        : "r"((a)[0]), "r"((a)[1]), "r"((a)[2]), "r"((a)[3]),             \
          "r"(b0v), "r"(b1v))

__global__ void __launch_bounds__(128, 2)
gru_mma(const float* __restrict__ precip,
        const float* __restrict__ temp,
        const float* __restrict__ wih,     // (192,2)
        const float* __restrict__ whh,     // (192,64)
        const float* __restrict__ bias,    // (192,)
        const float* __restrict__ bias_n,  // (64,)
        const float* __restrict__ out_w,   // (1,64)
        const float* __restrict__ out_b,   // (1,)
        const float* __restrict__ init_h,  // (64,)
        float* __restrict__ out)           // smb (365*65536) ++ final_h (65536*64)
{
    extern __shared__ char smem[];
    uint4* frag = (uint4*)smem;  // [tile = nt*4+kt][lane] -> {bhi0,bhi1,blo0,blo1}
    float* s_wih = (float*)(smem + FRAG_BYTES);
    float* s_bias = s_wih + 384;
    float* s_bn = s_bias + 192;
    float* s_ow = s_bn + 64;

    const int tid = threadIdx.x;
    const int warp = tid >> 5, lane = tid & 31;
    const int g = lane >> 2, tig = lane & 3;
    const int m_base = blockIdx.x * 64 + warp * 16;
    const int c0 = m_base + g;       // cell for D rows g
    const int c1 = c0 + 8;           // cell for D rows g+8

    for (int i = tid; i < 384; i += 128) s_wih[i] = wih[i];
    for (int i = tid; i < 192; i += 128) s_bias[i] = bias[i];
    if (tid < 64) { s_bn[tid] = bias_n[tid]; s_ow[tid] = out_w[tid]; }

    // Precompute B fragments (each warp fills 24 tiles; content lane-indexed).
    // B[k][n] = Whh[n][k]; thread(g,tig) of tile(nt,kt):
    //   b0 = {B[k],B[k+1]}@n=8nt+g with k=16kt+2tig, b1 = same at k+8.
    for (int tt = warp * 24; tt < warp * 24 + 24; tt++) {
        const int nt = tt >> 2, kt = tt & 3;
        const float* row = whh + (nt * 8 + g) * 64 + kt * 16 + tig * 2;
        const float w0 = row[0], w1 = row[1], w8 = row[8], w9 = row[9];
        const uint32_t h0r = pk_bf2(w1, w0);
        const uint32_t l0r = pk_bf2(w1 - hi16f(h0r), w0 - lo16f(h0r));
        const uint32_t h1r = pk_bf2(w9, w8);
        const uint32_t l1r = pk_bf2(w9 - hi16f(h1r), w8 - lo16f(h1r));
        frag[tt * 32 + lane] = make_uint4(h0r, h1r, l0r, l1r);
    }
    __syncthreads();

    // Hidden state fp32 in registers. Thread owns, per group ng (0..7),
    // hidden units j0=8ng+2tig and j0+1 for cells c0 and c1.
    float h0[16], h1[16];
    // A fragments: Ahi/Alo[kt*4 + slot], slot: 0={row g,k lo-pair},
    // 1={row g+8,k lo-pair}, 2={row g,k hi-pair}, 3={row g+8,k hi-pair}.
    uint32_t Ahi[16], Alo[16];
#pragma unroll
    for (int ng = 0; ng < 8; ng++) {
        const int j0 = ng * 8 + tig * 2;
        const float v0 = init_h[j0], v1 = init_h[j0 + 1];
        h0[ng * 2] = v0; h0[ng * 2 + 1] = v1;
        h1[ng * 2] = v0; h1[ng * 2 + 1] = v1;
        const uint32_t hp = pk_bf2(v1, v0);
        const uint32_t lp = pk_bf2(v1 - hi16f(hp), v0 - lo16f(hp));
        const int kt = ng >> 1, s = (ng & 1) * 2;
        Ahi[kt * 4 + s] = hp; Ahi[kt * 4 + s + 1] = hp;
        Alo[kt * 4 + s] = lp; Alo[kt * 4 + s + 1] = lp;
    }

    const float ob = out_b[0];

#pragma unroll 1
    for (int t = 0; t < TT; t++) {
        const float xp0 = precip[t * NC + c0], xt0 = temp[t * NC + c0];
        const float xp1 = precip[t * NC + c1], xt1 = temp[t * NC + c1];
        float y0 = 0.f, y1 = 0.f;

#pragma unroll
        for (int ng = 0; ng < 8; ng++) {
            // Two accumulators per gate tile (shorter HMMA dep chains).
            float drA[4] = {0, 0, 0, 0}, drB[4] = {0, 0, 0, 0};
            float dzA[4] = {0, 0, 0, 0}, dzB[4] = {0, 0, 0, 0};
            float dnA[4] = {0, 0, 0, 0}, dnB[4] = {0, 0, 0, 0};
#pragma unroll
            for (int kt = 0; kt < 4; kt++) {
                const uint4 br = frag[(ng * 4 + kt) * 32 + lane];
                const uint4 bz = frag[((ng + 8) * 4 + kt) * 32 + lane];
                const uint4 bn4 = frag[((ng + 16) * 4 + kt) * 32 + lane];
                const uint32_t* ah = &Ahi[kt * 4];
                const uint32_t* al = &Alo[kt * 4];
                MMA(drA, ah, br.x, br.y);    // Ahi * Bhi
                MMA(dzA, ah, bz.x, bz.y);
                MMA(dnA, ah, bn4.x, bn4.y);
                MMA(drB, al, br.x, br.y);    // Alo * Bhi
                MMA(dzB, al, bz.x, bz.y);
                MMA(dnB, al, bn4.x, bn4.y);
                MMA(drA, ah, br.z, br.w);    // Ahi * Blo
                MMA(dzA, ah, bz.z, bz.w);
                MMA(dnA, ah, bn4.z, bn4.w);
            }
            const int j0 = ng * 8 + tig * 2;
#pragma unroll
            for (int u = 0; u < 2; u++) {
                const int j = j0 + u;
                const float wa0 = s_wih[2 * j],       wa1 = s_wih[2 * j + 1];
                const float wb0 = s_wih[2 * j + 128], wb1 = s_wih[2 * j + 129];
                const float wc0 = s_wih[2 * j + 256], wc1 = s_wih[2 * j + 257];
                const float bR = s_bias[j], bZ = s_bias[j + 64], bN = s_bias[j + 128];
                const float bn2 = s_bn[j], ow = s_ow[j];
                // cell c0: D regs 0(u=0)/1(u=1); cell c1: 2/3.
                {
                    const float hr = drA[u] + drB[u];
                    const float hz = dzA[u] + dzB[u];
                    const float hn = dnA[u] + dnB[u];
                    const float r = sig_fast(fmaf(xp0, wa0, fmaf(xt0, wa1, bR)) + hr);
                    const float z = sig_fast(fmaf(xp0, wb0, fmaf(xt0, wb1, bZ)) + hz);
                    const float n = tanh_fast(
                        fmaf(r, hn + bn2, fmaf(xp0, wc0, fmaf(xt0, wc1, bN))));
                    const float hx = fmaf(z, h0[ng * 2 + u] - n, n);
                    h0[ng * 2 + u] = hx;
                    y0 = fmaf(hx, ow, y0);
                }
                {
                    const float hr = drA[2 + u] + drB[2 + u];
                    const float hz = dzA[2 + u] + dzB[2 + u];
                    const float hn = dnA[2 + u] + dnB[2 + u];
                    const float r = sig_fast(fmaf(xp1, wa0, fmaf(xt1, wa1, bR)) + hr);
                    const float z = sig_fast(fmaf(xp1, wb0, fmaf(xt1, wb1, bZ)) + hz);
                    const float n = tanh_fast(
                        fmaf(r, hn + bn2, fmaf(xp1, wc0, fmaf(xt1, wc1, bN))));
                    const float hx = fmaf(z, h1[ng * 2 + u] - n, n);
                    h1[ng * 2 + u] = hx;
                    y1 = fmaf(hx, ow, y1);
                }
            }
        }

        // Rebuild A fragments from the new h — AFTER all groups (every
        // group's MMA reads the full old-A K range).
#pragma unroll
        for (int ng = 0; ng < 8; ng++) {
            const int kt = ng >> 1, s = (ng & 1) * 2;
            const uint32_t hp0 = pk_bf2(h0[ng * 2 + 1], h0[ng * 2]);
            Ahi[kt * 4 + s] = hp0;
            Alo[kt * 4 + s] =
                pk_bf2(h0[ng * 2 + 1] - hi16f(hp0), h0[ng * 2] - lo16f(hp0));
            const uint32_t hp1 = pk_bf2(h1[ng * 2 + 1], h1[ng * 2]);
            Ahi[kt * 4 + s + 1] = hp1;
            Alo[kt * 4 + s + 1] =
                pk_bf2(h1[ng * 2 + 1] - hi16f(hp1), h1[ng * 2] - lo16f(hp1));
        }

        // y reduction across the 4-lane tig group (disjoint j coverage).
        y0 += __shfl_xor_sync(0xffffffffu, y0, 1);
        y0 += __shfl_xor_sync(0xffffffffu, y0, 2);
        y1 += __shfl_xor_sync(0xffffffffu, y1, 1);
        y1 += __shfl_xor_sync(0xffffffffu, y1, 2);
        if (tig == 0) {
            out[t * NC + c0] = y0 + ob;
            out[t * NC + c1] = y1 + ob;
        }
    }

    // final_h: (H, W, 64) contiguous per cell, after the smb block.
    {
        float2* f0 = (float2*)(out + (size_t)TT * NC + (size_t)c0 * 64);
        float2* f1 = (float2*)(out + (size_t)TT * NC + (size_t)c1 * 64);
#pragma unroll
        for (int ng = 0; ng < 8; ng++) {
            const int p = (ng * 8 + tig * 2) >> 1;  // float2 index
            f0[p] = make_float2(h0[ng * 2], h0[ng * 2 + 1]);
            f1[p] = make_float2(h1[ng * 2], h1[ng * 2 + 1]);
        }
    }
}

extern "C" void kernel_launch(void* const* d_in, const int* in_sizes, int n_in,
                              void* d_out, int out_size) {
    // Opt-in for >48KB dynamic smem. Immediate host-side call (no stream op,
    // no graph node, no allocation); idempotent across correctness + capture.
    cudaFuncSetAttribute(gru_mma, cudaFuncAttributeMaxDynamicSharedMemorySize,
                         SMEM_BYTES);
    gru_mma<<<NC / 64, 128, SMEM_BYTES>>>(
        (const float*)d_in[0],   // precipitation
        (const float*)d_in[1],   // temperature
        (const float*)d_in[2],   // weight_ih
        (const float*)d_in[3],   // weight_hh
        (const float*)d_in[4],   // bias
        (const float*)d_in[5],   // bias_n
        (const float*)d_in[6],   // out_w
        (const float*)d_in[7],   // out_b
        (const float*)d_in[8],   // init_h
        (float*)d_out);
}

// round 16
// speedup vs baseline: 12.7251x; 2.2322x over previous
#include <cuda_runtime.h>
#include <cuda_bf16.h>
#include <cstdint>

// GRU T=365, 65536 cells, HID=64 — mma.sync bf16, register-resident A/D.
//
// R13 post-mortem: fully-unrolled ng-loop -> 255 regs + spills (L2=34%),
// occ 11% -> tensor only 27%. This round: ng-loop ROLLED (small body), h
// staged in thread-private shared-memory slots (conflict-free, dynamic ng
// is just an address — no dynamic register indexing), launch_bounds(128,3)
// -> reg cap 168, 12 warps/SM.
//
// Math identical to R13: gates[16,192] = h[16,64] @ Whh^T per warp via
// m16n8k16 bf16, 3-pass hi/lo split (AhiBhi + AloBhi + AhiBlo), fp32 accum.
// D/A fragment (row, col mod 8) ownership coincide and r/z/n gates sit at
// j, j+64, j+128 (same mod 8) -> epilogue is thread-local.

#define NC (256 * 256)
#define TT 365
#define FRAG_BYTES (96 * 32 * 16)            // 49152: B-fragment table
#define STAGE_BYTES (16 * 128 * 8)           // 16384: float2 stage[16][128]
#define PARAM_BYTES ((384 + 192 + 64 + 64) * 4)
#define SMEM_BYTES (FRAG_BYTES + STAGE_BYTES + PARAM_BYTES)  // 68352

__device__ __forceinline__ uint32_t pk_bf2(float up, float lo) {
    uint32_t r;
    asm("cvt.rn.bf16x2.f32 %0, %1, %2;" : "=r"(r) : "f"(up), "f"(lo));
    return r;
}
__device__ __forceinline__ float lo16f(uint32_t r) { return __uint_as_float(r << 16); }
__device__ __forceinline__ float hi16f(uint32_t r) { return __uint_as_float(r & 0xffff0000u); }

__device__ __forceinline__ float tanh_fast(float x) {
    float r;
    asm("tanh.approx.f32 %0, %1;" : "=f"(r) : "f"(x));
    return r;
}
__device__ __forceinline__ float sig_fast(float x) {
    return fmaf(0.5f, tanh_fast(0.5f * x), 0.5f);
}

#define MMA(d, a, b0v, b1v)                                               \
    asm("mma.sync.aligned.m16n8k16.row.col.f32.bf16.bf16.f32 "            \
        "{%0,%1,%2,%3}, {%4,%5,%6,%7}, {%8,%9}, {%0,%1,%2,%3};"           \
        : "+f"((d)[0]), "+f"((d)[1]), "+f"((d)[2]), "+f"((d)[3])          \
        : "r"((a)[0]), "r"((a)[1]), "r"((a)[2]), "r"((a)[3]),             \
          "r"(b0v), "r"(b1v))

__global__ void __launch_bounds__(128, 3)
gru_mma(const float* __restrict__ precip,
        const float* __restrict__ temp,
        const float* __restrict__ wih,     // (192,2)
        const float* __restrict__ whh,     // (192,64)
        const float* __restrict__ bias,    // (192,)
        const float* __restrict__ bias_n,  // (64,)
        const float* __restrict__ out_w,   // (1,64)
        const float* __restrict__ out_b,   // (1,)
        const float* __restrict__ init_h,  // (64,)
        float* __restrict__ out)           // smb (365*65536) ++ final_h (65536*64)
{
    extern __shared__ char smem[];
    uint4* frag = (uint4*)smem;                       // [tile][lane]
    float2* stage = (float2*)(smem + FRAG_BYTES);     // [cs*8+ng][tid]
    float* s_wih = (float*)(smem + FRAG_BYTES + STAGE_BYTES);
    float* s_bias = s_wih + 384;
    float* s_bn = s_bias + 192;
    float* s_ow = s_bn + 64;

    const int tid = threadIdx.x;
    const int warp = tid >> 5, lane = tid & 31;
    const int g = lane >> 2, tig = lane & 3;
    const int m_base = blockIdx.x * 64 + warp * 16;
    const int c0 = m_base + g;       // cell for D rows g
    const int c1 = c0 + 8;           // cell for D rows g+8

    for (int i = tid; i < 384; i += 128) s_wih[i] = wih[i];
    for (int i = tid; i < 192; i += 128) s_bias[i] = bias[i];
    if (tid < 64) { s_bn[tid] = bias_n[tid]; s_ow[tid] = out_w[tid]; }

    // B fragments: B[k][n] = Whh[n][k]; thread(g,tig) of tile(nt,kt):
    //   b0 = {B[k],B[k+1]}@n=8nt+g with k=16kt+2tig, b1 = same at k+8.
    for (int tt = warp * 24; tt < warp * 24 + 24; tt++) {
        const int nt = tt >> 2, kt = tt & 3;
        const float* row = whh + (nt * 8 + g) * 64 + kt * 16 + tig * 2;
        const float w0 = row[0], w1 = row[1], w8 = row[8], w9 = row[9];
        const uint32_t h0r = pk_bf2(w1, w0);
        const uint32_t l0r = pk_bf2(w1 - hi16f(h0r), w0 - lo16f(h0r));
        const uint32_t h1r = pk_bf2(w9, w8);
        const uint32_t l1r = pk_bf2(w9 - hi16f(h1r), w8 - lo16f(h1r));
        frag[tt * 32 + lane] = make_uint4(h0r, h1r, l0r, l1r);
    }
    __syncthreads();

    // A fragments: Ahi/Alo[kt*4 + slot], slot 0={row g,k-lo}, 1={row g+8,
    // k-lo}, 2={row g,k-hi}, 3={row g+8,k-hi}. h itself lives in the smem
    // stage (thread-private slots; fp32 exact).
    uint32_t Ahi[16], Alo[16];
#pragma unroll
    for (int ng = 0; ng < 8; ng++) {
        const int j0 = ng * 8 + tig * 2;
        const float v0 = init_h[j0], v1 = init_h[j0 + 1];
        stage[ng * 128 + tid] = make_float2(v0, v1);          // cell c0
        stage[(8 + ng) * 128 + tid] = make_float2(v0, v1);    // cell c1
        const uint32_t hp = pk_bf2(v1, v0);
        const uint32_t lp = pk_bf2(v1 - hi16f(hp), v0 - lo16f(hp));
        const int kt = ng >> 1, s = (ng & 1) * 2;
        Ahi[kt * 4 + s] = hp; Ahi[kt * 4 + s + 1] = hp;
        Alo[kt * 4 + s] = lp; Alo[kt * 4 + s + 1] = lp;
    }

    const float ob = out_b[0];

#pragma unroll 1
    for (int t = 0; t < TT; t++) {
        const float xp0 = precip[t * NC + c0], xt0 = temp[t * NC + c0];
        const float xp1 = precip[t * NC + c1], xt1 = temp[t * NC + c1];
        float y0 = 0.f, y1 = 0.f;

#pragma unroll 1
        for (int ng = 0; ng < 8; ng++) {
            float drA[4] = {0, 0, 0, 0}, drB[4] = {0, 0, 0, 0};
            float dzA[4] = {0, 0, 0, 0}, dzB[4] = {0, 0, 0, 0};
            float dnA[4] = {0, 0, 0, 0}, dnB[4] = {0, 0, 0, 0};
#pragma unroll
            for (int kt = 0; kt < 4; kt++) {
                const uint4 br = frag[(ng * 4 + kt) * 32 + lane];
                const uint4 bz = frag[((ng + 8) * 4 + kt) * 32 + lane];
                const uint4 bn4 = frag[((ng + 16) * 4 + kt) * 32 + lane];
                const uint32_t* ah = &Ahi[kt * 4];
                const uint32_t* al = &Alo[kt * 4];
                MMA(drA, ah, br.x, br.y);    // Ahi * Bhi
                MMA(dzA, ah, bz.x, bz.y);
                MMA(dnA, ah, bn4.x, bn4.y);
                MMA(drB, al, br.x, br.y);    // Alo * Bhi
                MMA(dzB, al, bz.x, bz.y);
                MMA(dnB, al, bn4.x, bn4.y);
                MMA(drA, ah, br.z, br.w);    // Ahi * Blo
                MMA(dzA, ah, bz.z, bz.w);
                MMA(dnA, ah, bn4.z, bn4.w);
            }
            const int j0 = ng * 8 + tig * 2;
            const float wa0 = s_wih[2 * j0],       wa1 = s_wih[2 * j0 + 1];
            const float wa2 = s_wih[2 * j0 + 2],   wa3 = s_wih[2 * j0 + 3];
            const float wb0 = s_wih[2 * j0 + 128], wb1 = s_wih[2 * j0 + 129];
            const float wb2 = s_wih[2 * j0 + 130], wb3 = s_wih[2 * j0 + 131];
            const float wc0 = s_wih[2 * j0 + 256], wc1 = s_wih[2 * j0 + 257];
            const float wc2 = s_wih[2 * j0 + 258], wc3 = s_wih[2 * j0 + 259];
            const float bR0 = s_bias[j0],       bR1 = s_bias[j0 + 1];
            const float bZ0 = s_bias[j0 + 64],  bZ1 = s_bias[j0 + 65];
            const float bN0 = s_bias[j0 + 128], bN1 = s_bias[j0 + 129];
            const float bn20 = s_bn[j0], bn21 = s_bn[j0 + 1];
            const float ow0 = s_ow[j0], ow1 = s_ow[j0 + 1];

            // ---- cell c0 (D regs 0,1) ----
            {
                const float2 holdv = stage[ng * 128 + tid];
                const float r0 = sig_fast(fmaf(xp0, wa0, fmaf(xt0, wa1, bR0)) + drA[0] + drB[0]);
                const float z0 = sig_fast(fmaf(xp0, wb0, fmaf(xt0, wb1, bZ0)) + dzA[0] + dzB[0]);
                const float n0 = tanh_fast(fmaf(r0, dnA[0] + dnB[0] + bn20,
                                                fmaf(xp0, wc0, fmaf(xt0, wc1, bN0))));
                const float r1 = sig_fast(fmaf(xp0, wa2, fmaf(xt0, wa3, bR1)) + drA[1] + drB[1]);
                const float z1 = sig_fast(fmaf(xp0, wb2, fmaf(xt0, wb3, bZ1)) + dzA[1] + dzB[1]);
                const float n1 = tanh_fast(fmaf(r1, dnA[1] + dnB[1] + bn21,
                                                fmaf(xp0, wc2, fmaf(xt0, wc3, bN1))));
                const float hx0 = fmaf(z0, holdv.x - n0, n0);
                const float hx1 = fmaf(z1, holdv.y - n1, n1);
                stage[ng * 128 + tid] = make_float2(hx0, hx1);
                y0 = fmaf(hx0, ow0, fmaf(hx1, ow1, y0));
            }
            // ---- cell c1 (D regs 2,3) ----
            {
                const float2 holdv = stage[(8 + ng) * 128 + tid];
                const float r0 = sig_fast(fmaf(xp1, wa0, fmaf(xt1, wa1, bR0)) + drA[2] + drB[2]);
                const float z0 = sig_fast(fmaf(xp1, wb0, fmaf(xt1, wb1, bZ0)) + dzA[2] + dzB[2]);
                const float n0 = tanh_fast(fmaf(r0, dnA[2] + dnB[2] + bn20,
                                                fmaf(xp1, wc0, fmaf(xt1, wc1, bN0))));
                const float r1 = sig_fast(fmaf(xp1, wa2, fmaf(xt1, wa3, bR1)) + drA[3] + drB[3]);
                const float z1 = sig_fast(fmaf(xp1, wb2, fmaf(xt1, wb3, bZ1)) + dzA[3] + dzB[3]);
                const float n1 = tanh_fast(fmaf(r1, dnA[3] + dnB[3] + bn21,
                                                fmaf(xp1, wc2, fmaf(xt1, wc3, bN1))));
                const float hx0 = fmaf(z0, holdv.x - n0, n0);
                const float hx1 = fmaf(z1, holdv.y - n1, n1);
                stage[(8 + ng) * 128 + tid] = make_float2(hx0, hx1);
                y1 = fmaf(hx0, ow0, fmaf(hx1, ow1, y1));
            }
        }

        // Rebuild A fragments from the stage (thread reads only its own
        // slots — the A-fragment k-positions coincide with the j-positions
        // this thread computed). Static Ahi/Alo indices via unrolled loop.
#pragma unroll
        for (int ng = 0; ng < 8; ng++) {
            const int kt = ng >> 1, s = (ng & 1) * 2;
            const float2 v0 = stage[ng * 128 + tid];
            const uint32_t hp0 = pk_bf2(v0.y, v0.x);
            Ahi[kt * 4 + s] = hp0;
            Alo[kt * 4 + s] = pk_bf2(v0.y - hi16f(hp0), v0.x - lo16f(hp0));
            const float2 v1 = stage[(8 + ng) * 128 + tid];
            const uint32_t hp1 = pk_bf2(v1.y, v1.x);
            Ahi[kt * 4 + s + 1] = hp1;
            Alo[kt * 4 + s + 1] = pk_bf2(v1.y - hi16f(hp1), v1.x - lo16f(hp1));
        }

        // y reduction across the 4-lane tig group (disjoint j coverage).
        y0 += __shfl_xor_sync(0xffffffffu, y0, 1);
        y0 += __shfl_xor_sync(0xffffffffu, y0, 2);
        y1 += __shfl_xor_sync(0xffffffffu, y1, 1);
        y1 += __shfl_xor_sync(0xffffffffu, y1, 2);
        if (tig == 0) {
            out[t * NC + c0] = y0 + ob;
            out[t * NC + c1] = y1 + ob;
        }
    }

    // final_h: (H, W, 64) contiguous per cell, after the smb block.
    {
        float2* f0 = (float2*)(out + (size_t)TT * NC + (size_t)c0 * 64);
        float2* f1 = (float2*)(out + (size_t)TT * NC + (size_t)c1 * 64);
#pragma unroll
        for (int ng = 0; ng < 8; ng++) {
            const int p = (ng * 8 + tig * 2) >> 1;  // float2 index
            f0[p] = stage[ng * 128 + tid];
            f1[p] = stage[(8 + ng) * 128 + tid];
        }
    }
}

extern "C" void kernel_launch(void* const* d_in, const int* in_sizes, int n_in,
                              void* d_out, int out_size) {
    cudaFuncSetAttribute(gru_mma, cudaFuncAttributeMaxDynamicSharedMemorySize,
                         SMEM_BYTES);
    gru_mma<<<NC / 64, 128, SMEM_BYTES>>>(
        (const float*)d_in[0],   // precipitation
        (const float*)d_in[1],   // temperature
        (const float*)d_in[2],   // weight_ih
        (const float*)d_in[3],   // weight_hh
        (const float*)d_in[4],   // bias
        (const float*)d_in[5],   // bias_n
        (const float*)d_in[6],   // out_w
        (const float*)d_in[7],   // out_b
        (const float*)d_in[8],   // init_h
        (float*)d_out);
}